// round 8
// baseline (speedup 1.0000x reference)
#include <cuda_runtime.h>
#include <math.h>

#define S 2048
#define D 512
#define H 8
#define DH 64
#define L 4
#define FF 2048

// ---------------- scratch (static device globals; no allocation) ----------------
__device__ float d_x  [S * D];
__device__ float d_y  [S * D];
__device__ float d_q  [S * D];
__device__ float d_k  [S * D];
__device__ float d_v  [S * D];
__device__ float d_g  [S * D];
__device__ float d_ret[S * D];
__device__ float d_ff [S * FF];
__device__ float d_sin[S * (DH / 2)];
__device__ float d_cos[S * (DH / 2)];
__device__ float d_gpow[H * S];

// ---------------- setup tables (double precision, matches numpy float64) --------
__global__ void init_tables_kernel() {
    int idx = blockIdx.x * blockDim.x + threadIdx.x;
    if (idx < S * (DH / 2)) {
        int s = idx / (DH / 2);
        int j = idx % (DH / 2);
        double theta = pow(10000.0, -(double)(2 * j) / (double)DH);
        double ang = (double)s * theta;
        d_sin[idx] = (float)sin(ang);
        d_cos[idx] = (float)cos(ang);
    }
    if (idx < H * S) {
        int h = idx / S;
        int dd = idx % S;
        double lg0 = log(1.0 / 32.0);
        double lg1 = log(1.0 / 512.0);
        double gamma = 1.0 - exp(lg0 + (lg1 - lg0) * (double)h / 7.0);
        d_gpow[idx] = (float)exp((double)dd * log(gamma));
    }
}

// x = x_in + pos_emb[0]  (reference broadcasts pos_emb[:B] with B==1)
__global__ void add_pos_kernel(const float* __restrict__ x, const float* __restrict__ pe) {
    int i = blockIdx.x * blockDim.x + threadIdx.x;
    if (i < S * D) d_x[i] = x[i] + pe[i % D];
}

// ---------------- layernorm: one block per row, D=512, 256 threads --------------
__global__ void layernorm_kernel(const float* __restrict__ in,
                                 const float* __restrict__ w,
                                 const float* __restrict__ b,
                                 float* __restrict__ out, float eps) {
    int row = blockIdx.x;
    int t = threadIdx.x;
    const float* xr = in + row * D;
    __shared__ float red[256];

    float v0 = xr[t];
    float v1 = xr[t + 256];
    red[t] = v0 + v1;
    __syncthreads();
    for (int o = 128; o > 0; o >>= 1) {
        if (t < o) red[t] += red[t + o];
        __syncthreads();
    }
    float mu = red[0] * (1.0f / D);
    __syncthreads();
    float a0 = v0 - mu, a1 = v1 - mu;
    red[t] = a0 * a0 + a1 * a1;
    __syncthreads();
    for (int o = 128; o > 0; o >>= 1) {
        if (t < o) red[t] += red[t + o];
        __syncthreads();
    }
    float rstd = rsqrtf(red[0] * (1.0f / D) + eps);
    out[row * D + t]       = a0 * rstd * w[t]       + b[t];
    out[row * D + t + 256] = a1 * rstd * w[t + 256] + b[t + 256];
}

// ---------------- fp32 SGEMM: C[M,N] = epi(A[M,K] @ W[K,N] + bias) ---------------
// EPI: 0 = plain, 1 = SiLU, 2 = residual add (C += result)
// BM=64 BN=64 BK=16, 256 threads, 4x4 microtile. M,N%64==0, K%16==0 assumed.
template <int EPI>
__global__ void gemm_kernel(const float* __restrict__ A, const float* __restrict__ W,
                            const float* __restrict__ bias, float* __restrict__ C,
                            int M, int N, int K) {
    __shared__ float As[16][68];
    __shared__ float Ws[16][68];

    int tid = threadIdx.x;
    int tx = tid & 15;
    int ty = tid >> 4;
    int row0 = blockIdx.y * 64;
    int col0 = blockIdx.x * 64;

    int ar = tid >> 2;            // 0..63
    int ac = (tid & 3) * 4;       // 0,4,8,12
    int wr = tid >> 4;            // 0..15
    int wc = (tid & 15) * 4;      // 0..60

    float acc[4][4] = {};

    for (int k0 = 0; k0 < K; k0 += 16) {
        float4 av = *(const float4*)&A[(row0 + ar) * K + k0 + ac];
        As[ac + 0][ar] = av.x;
        As[ac + 1][ar] = av.y;
        As[ac + 2][ar] = av.z;
        As[ac + 3][ar] = av.w;
        float4 wv = *(const float4*)&W[(k0 + wr) * N + col0 + wc];
        *(float4*)&Ws[wr][wc] = wv;
        __syncthreads();

#pragma unroll
        for (int kk = 0; kk < 16; kk++) {
            float a0 = As[kk][ty * 4 + 0];
            float a1 = As[kk][ty * 4 + 1];
            float a2 = As[kk][ty * 4 + 2];
            float a3 = As[kk][ty * 4 + 3];
            float b0 = Ws[kk][tx * 4 + 0];
            float b1 = Ws[kk][tx * 4 + 1];
            float b2 = Ws[kk][tx * 4 + 2];
            float b3 = Ws[kk][tx * 4 + 3];
            acc[0][0] += a0 * b0; acc[0][1] += a0 * b1; acc[0][2] += a0 * b2; acc[0][3] += a0 * b3;
            acc[1][0] += a1 * b0; acc[1][1] += a1 * b1; acc[1][2] += a1 * b2; acc[1][3] += a1 * b3;
            acc[2][0] += a2 * b0; acc[2][1] += a2 * b1; acc[2][2] += a2 * b2; acc[2][3] += a2 * b3;
            acc[3][0] += a3 * b0; acc[3][1] += a3 * b1; acc[3][2] += a3 * b2; acc[3][3] += a3 * b3;
        }
        __syncthreads();
    }

#pragma unroll
    for (int r = 0; r < 4; r++) {
        int row = row0 + ty * 4 + r;
#pragma unroll
        for (int c = 0; c < 4; c++) {
            int col = col0 + tx * 4 + c;
            float val = acc[r][c] + bias[col];
            if (EPI == 1) val = val / (1.0f + expf(-val));      // SiLU
            if (EPI == 2) val += C[row * N + col];              // residual
            C[row * N + col] = val;
        }
    }
}

// ---------------- RoPE-style theta shift (in place), optional scale --------------
__global__ void rope_kernel(float* __restrict__ q, float scale) {
    int idx = blockIdx.x * blockDim.x + threadIdx.x;   // S*H*32
    if (idx >= S * H * (DH / 2)) return;
    int j = idx & 31;
    int h = (idx >> 5) & (H - 1);
    int s = idx >> 8;
    float c  = d_cos[s * 32 + j];
    float sn = d_sin[s * 32 + j];
    int base = s * D + h * DH + 2 * j;
    float x0 = q[base];
    float x1 = q[base + 1];
    q[base]     = (x0 * c - x1 * sn) * scale;
    q[base + 1] = (x1 * c + x0 * sn) * scale;
}

// ---------------- retention: flash-style causal decay attention + groupnorm ------
// grid: (S/64, H), block 256. Per block: 64 queries x DH=64, stream 32-key tiles.
__global__ void attn_kernel(const float* __restrict__ q, const float* __restrict__ k,
                            const float* __restrict__ v, float* __restrict__ ret) {
    __shared__ float qs[64][65];
    __shared__ float ks[32][65];
    __shared__ float vs[32][65];
    __shared__ float ss[64][33];

    int h = blockIdx.y;
    int s0 = blockIdx.x * 64;
    int tid = threadIdx.x;

    // load Q tile (64 x 64)
    for (int i = tid; i < 64 * 16; i += 256) {
        int r = i >> 4;
        int c4 = (i & 15) * 4;
        float4 t = *(const float4*)&q[(s0 + r) * D + h * DH + c4];
        qs[r][c4 + 0] = t.x; qs[r][c4 + 1] = t.y; qs[r][c4 + 2] = t.z; qs[r][c4 + 3] = t.w;
    }

    int aty = tid >> 4, atx = tid & 15;   // phase A: rows aty*4.., cols atx*2..
    int bty = tid >> 4, btx = tid & 15;   // phase B: rows bty*4.., cols btx*4..
    float acc[4][4] = {};

    const float* gp = d_gpow + h * S;
    int ntiles = s0 / 32 + 2;             // key tiles with m0 <= s0+63
    __syncthreads();

    for (int t = 0; t < ntiles; t++) {
        int m0 = t * 32;
        // load K,V tiles (32 x 64 each)
        for (int i = tid; i < 32 * 16; i += 256) {
            int r = i >> 4;
            int c4 = (i & 15) * 4;
            float4 kv = *(const float4*)&k[(m0 + r) * D + h * DH + c4];
            ks[r][c4 + 0] = kv.x; ks[r][c4 + 1] = kv.y; ks[r][c4 + 2] = kv.z; ks[r][c4 + 3] = kv.w;
            float4 vv = *(const float4*)&v[(m0 + r) * D + h * DH + c4];
            vs[r][c4 + 0] = vv.x; vs[r][c4 + 1] = vv.y; vs[r][c4 + 2] = vv.z; vs[r][c4 + 3] = vv.w;
        }
        __syncthreads();

        // phase A: s = q @ k^T (4 rows x 2 cols per thread)
        float sv[4][2] = {};
#pragma unroll 16
        for (int d = 0; d < 64; d++) {
            float qr0 = qs[aty * 4 + 0][d];
            float qr1 = qs[aty * 4 + 1][d];
            float qr2 = qs[aty * 4 + 2][d];
            float qr3 = qs[aty * 4 + 3][d];
            float kc0 = ks[atx * 2 + 0][d];
            float kc1 = ks[atx * 2 + 1][d];
            sv[0][0] += qr0 * kc0; sv[0][1] += qr0 * kc1;
            sv[1][0] += qr1 * kc0; sv[1][1] += qr1 * kc1;
            sv[2][0] += qr2 * kc0; sv[2][1] += qr2 * kc1;
            sv[3][0] += qr3 * kc0; sv[3][1] += qr3 * kc1;
        }
#pragma unroll
        for (int r = 0; r < 4; r++) {
#pragma unroll
            for (int c = 0; c < 2; c++) {
                int qi = s0 + aty * 4 + r;
                int kj = m0 + atx * 2 + c;
                int dist = qi - kj;
                ss[aty * 4 + r][atx * 2 + c] = (dist >= 0) ? sv[r][c] * gp[dist] : 0.0f;
            }
        }
        __syncthreads();

        // phase B: acc += s @ v
#pragma unroll 8
        for (int j = 0; j < 32; j++) {
            float vr0 = vs[j][btx * 4 + 0];
            float vr1 = vs[j][btx * 4 + 1];
            float vr2 = vs[j][btx * 4 + 2];
            float vr3 = vs[j][btx * 4 + 3];
            float s0r = ss[bty * 4 + 0][j];
            float s1r = ss[bty * 4 + 1][j];
            float s2r = ss[bty * 4 + 2][j];
            float s3r = ss[bty * 4 + 3][j];
            acc[0][0] += s0r * vr0; acc[0][1] += s0r * vr1; acc[0][2] += s0r * vr2; acc[0][3] += s0r * vr3;
            acc[1][0] += s1r * vr0; acc[1][1] += s1r * vr1; acc[1][2] += s1r * vr2; acc[1][3] += s1r * vr3;
            acc[2][0] += s2r * vr0; acc[2][1] += s2r * vr1; acc[2][2] += s2r * vr2; acc[2][3] += s2r * vr3;
            acc[3][0] += s3r * vr0; acc[3][1] += s3r * vr1; acc[3][2] += s3r * vr2; acc[3][3] += s3r * vr3;
        }
        __syncthreads();
    }

    // write acc into qs (Q no longer needed), then per-row groupnorm over DH
#pragma unroll
    for (int r = 0; r < 4; r++)
#pragma unroll
        for (int c = 0; c < 4; c++)
            qs[bty * 4 + r][btx * 4 + c] = acc[r][c];
    __syncthreads();

    if (tid < 64) {
        int i = tid;
        float mu = 0.0f;
#pragma unroll 16
        for (int d = 0; d < 64; d++) mu += qs[i][d];
        mu *= (1.0f / 64.0f);
        float var = 0.0f;
#pragma unroll 16
        for (int d = 0; d < 64; d++) {
            float dd = qs[i][d] - mu;
            var += dd * dd;
        }
        var *= (1.0f / 64.0f);
        float rs = rsqrtf(var + 1e-6f);
#pragma unroll 16
        for (int d = 0; d < 64; d++)
            ret[(s0 + i) * D + h * DH + d] = (qs[i][d] - mu) * rs;
    }
}

// ---------------- elementwise: g *= ret ----------------
__global__ void mul_kernel() {
    int i = blockIdx.x * blockDim.x + threadIdx.x;
    if (i < S * D) d_g[i] *= d_ret[i];
}

// ---------------- final: out[s] = sigmoid(x[s,:] . Wout + bout) ----------------
__global__ void final_kernel(const float* __restrict__ Wout, const float* __restrict__ bout,
                             float* __restrict__ out) {
    int row = blockIdx.x;
    int t = threadIdx.x;   // 64
    float s = 0.0f;
    for (int i = t; i < D; i += 64) s += d_x[row * D + i] * Wout[i];
    __shared__ float red[64];
    red[t] = s;
    __syncthreads();
    for (int o = 32; o > 0; o >>= 1) {
        if (t < o) red[t] += red[t + o];
        __syncthreads();
    }
    if (t == 0) out[row] = 1.0f / (1.0f + expf(-(red[0] + bout[0])));
}

// ---------------- host orchestration ----------------
extern "C" void kernel_launch(void* const* d_in, const int* in_sizes, int n_in,
                              void* d_out, int out_size) {
    const float* x_in  = (const float*)d_in[0];
    const float* pe    = (const float*)d_in[1];
    const float* Wq    = (const float*)d_in[2];
    const float* bq    = (const float*)d_in[3];
    const float* Wk    = (const float*)d_in[4];
    const float* bk    = (const float*)d_in[5];
    const float* Wv    = (const float*)d_in[6];
    const float* bv    = (const float*)d_in[7];
    const float* Wg    = (const float*)d_in[8];
    const float* bg    = (const float*)d_in[9];
    const float* Wo    = (const float*)d_in[10];
    const float* bo    = (const float*)d_in[11];
    const float* ln1w  = (const float*)d_in[12];
    const float* ln1b  = (const float*)d_in[13];
    const float* ln2w  = (const float*)d_in[14];
    const float* ln2b  = (const float*)d_in[15];
    const float* W1    = (const float*)d_in[16];
    const float* b1    = (const float*)d_in[17];
    const float* W2    = (const float*)d_in[18];
    const float* b2    = (const float*)d_in[19];
    const float* Wout  = (const float*)d_in[20];
    const float* bout  = (const float*)d_in[21];
    float* out = (float*)d_out;

    // device-global scratch addresses
    void *px_, *py_, *pq_, *pk_, *pv_, *pg_, *pret_, *pff_;
    cudaGetSymbolAddress(&px_,  d_x);
    cudaGetSymbolAddress(&py_,  d_y);
    cudaGetSymbolAddress(&pq_,  d_q);
    cudaGetSymbolAddress(&pk_,  d_k);
    cudaGetSymbolAddress(&pv_,  d_v);
    cudaGetSymbolAddress(&pg_,  d_g);
    cudaGetSymbolAddress(&pret_, d_ret);
    cudaGetSymbolAddress(&pff_, d_ff);
    float* px   = (float*)px_;
    float* py   = (float*)py_;
    float* pq   = (float*)pq_;
    float* pk   = (float*)pk_;
    float* pv   = (float*)pv_;
    float* pg   = (float*)pg_;
    float* pret = (float*)pret_;
    float* pff  = (float*)pff_;

    const float inv_scale = 0.125f;   // 1/sqrt(DH)

    init_tables_kernel<<<(S * 32 + 255) / 256, 256>>>();
    add_pos_kernel<<<(S * D + 255) / 256, 256>>>(x_in, pe);

    dim3 gemm_blk(256);
    dim3 grid_proj(D / 64, S / 64);    // N=512
    dim3 grid_ff1(FF / 64, S / 64);    // N=2048
    dim3 grid_ff2(D / 64, S / 64);

    for (int l = 0; l < L; l++) {
        // y = LN1(x)
        layernorm_kernel<<<S, 256>>>(px, ln1w + l * D, ln1b + l * D, py, 1e-5f);

        // q,k,v projections; g = silu(y@Wg+bg)
        gemm_kernel<0><<<grid_proj, gemm_blk>>>(py, Wq + l * D * D, bq + l * D, pq, S, D, D);
        gemm_kernel<0><<<grid_proj, gemm_blk>>>(py, Wk + l * D * D, bk + l * D, pk, S, D, D);
        gemm_kernel<0><<<grid_proj, gemm_blk>>>(py, Wv + l * D * D, bv + l * D, pv, S, D, D);
        gemm_kernel<1><<<grid_proj, gemm_blk>>>(py, Wg + l * D * D, bg + l * D, pg, S, D, D);

        // theta shift; q also scaled by 1/sqrt(DH)
        rope_kernel<<<(S * H * 32 + 255) / 256, 256>>>(pq, inv_scale);
        rope_kernel<<<(S * H * 32 + 255) / 256, 256>>>(pk, 1.0f);

        // retention + per-head groupnorm
        attn_kernel<<<dim3(S / 64, H), 256>>>(pq, pk, pv, pret);

        // g *= ret; x += (g*ret) @ Wo + bo
        mul_kernel<<<(S * D + 255) / 256, 256>>>();
        gemm_kernel<2><<<grid_proj, gemm_blk>>>(pg, Wo + l * D * D, bo + l * D, px, S, D, D);

        // FFN: z = LN2(x); x += silu(z@W1+b1) @ W2 + b2
        layernorm_kernel<<<S, 256>>>(px, ln2w + l * D, ln2b + l * D, py, 1e-5f);
        gemm_kernel<1><<<grid_ff1, gemm_blk>>>(py, W1 + l * D * FF, b1 + l * FF, pff, S, FF, D);
        gemm_kernel<2><<<grid_ff2, gemm_blk>>>(pff, W2 + l * FF * D, b2 + l * D, px, S, D, FF);
    }

    final_kernel<<<S, 64>>>(Wout, bout, out);
}

// round 9
// speedup vs baseline: 1.6323x; 1.6323x over previous
#include <cuda_runtime.h>
#include <math.h>

#define S 2048
#define D 512
#define H 8
#define DH 64
#define L 4
#define FF 2048
#define NC (S / 64)          // 32 chunks of 64

typedef unsigned long long ull;

// ---------------- scratch (static device globals; no allocation) ----------------
__device__ float d_x  [S * D];
__device__ float d_y  [S * D];
__device__ float d_q  [S * D];
__device__ float d_k  [S * D];
__device__ float d_v  [S * D];
__device__ float d_g  [S * D];
__device__ float d_ret[S * D];
__device__ float d_ff [S * FF];
__device__ float d_sin[S * (DH / 2)];
__device__ float d_cos[S * (DH / 2)];
__device__ float d_gpow[H * S];
__device__ float d_U[H * NC * DH * DH];   // per-chunk decayed k^T v
__device__ float d_M[H * NC * DH * DH];   // prefix states

// ---------------- f32x2 helpers ----------------
__device__ __forceinline__ ull dup2(float x) {
    ull r; asm("mov.b64 %0, {%1, %1};" : "=l"(r) : "f"(x)); return r;
}
__device__ __forceinline__ void ff2(ull& d, ull a, ull b) {
    asm("fma.rn.f32x2 %0, %1, %2, %0;" : "+l"(d) : "l"(a), "l"(b));
}
__device__ __forceinline__ float2 unpack2(ull p) {
    float2 r; asm("mov.b64 {%0, %1}, %2;" : "=f"(r.x), "=f"(r.y) : "l"(p)); return r;
}

// ---------------- setup tables (double precision, matches numpy float64) --------
__global__ void init_tables_kernel() {
    int idx = blockIdx.x * blockDim.x + threadIdx.x;
    if (idx < S * (DH / 2)) {
        int s = idx / (DH / 2);
        int j = idx % (DH / 2);
        double theta = pow(10000.0, -(double)(2 * j) / (double)DH);
        double ang = (double)s * theta;
        d_sin[idx] = (float)sin(ang);
        d_cos[idx] = (float)cos(ang);
    }
    if (idx < H * S) {
        int h = idx / S;
        int dd = idx % S;
        double lg0 = log(1.0 / 32.0);
        double lg1 = log(1.0 / 512.0);
        double gamma = 1.0 - exp(lg0 + (lg1 - lg0) * (double)h / 7.0);
        d_gpow[idx] = (float)exp((double)dd * log(gamma));
    }
}

__global__ void add_pos_kernel(const float* __restrict__ x, const float* __restrict__ pe) {
    int i = blockIdx.x * blockDim.x + threadIdx.x;
    if (i < S * D) d_x[i] = x[i] + pe[i % D];
}

// ---------------- layernorm ----------------
__global__ void layernorm_kernel(const float* __restrict__ in,
                                 const float* __restrict__ w,
                                 const float* __restrict__ b,
                                 float* __restrict__ out, float eps) {
    int row = blockIdx.x;
    int t = threadIdx.x;
    const float* xr = in + row * D;
    __shared__ float red[256];

    float v0 = xr[t];
    float v1 = xr[t + 256];
    red[t] = v0 + v1;
    __syncthreads();
    for (int o = 128; o > 0; o >>= 1) {
        if (t < o) red[t] += red[t + o];
        __syncthreads();
    }
    float mu = red[0] * (1.0f / D);
    __syncthreads();
    float a0 = v0 - mu, a1 = v1 - mu;
    red[t] = a0 * a0 + a1 * a1;
    __syncthreads();
    for (int o = 128; o > 0; o >>= 1) {
        if (t < o) red[t] += red[t + o];
        __syncthreads();
    }
    float rstd = rsqrtf(red[0] * (1.0f / D) + eps);
    out[row * D + t]       = a0 * rstd * w[t]       + b[t];
    out[row * D + t + 256] = a1 * rstd * w[t + 256] + b[t + 256];
}

// ================= f32x2 GEMM core: BM=128, BN=128, BK=16, 256 thr, 8x8 micro ====
template <int N, int K>
__device__ __forceinline__ void gemm128_accum(const float* __restrict__ A,
                                              const float* __restrict__ W,
                                              float (*As)[132], float (*Bs)[128],
                                              ull (&acc)[8][4]) {
    const int tid = threadIdx.x;
    const int row0 = blockIdx.y * 128;
    const int col0 = blockIdx.x * 128;
    const int arow = tid >> 1, ac8 = (tid & 1) * 8;
    const int brow = tid >> 4, bcol = (tid & 15) * 8;
    const int tx = tid & 15, ty = tid >> 4;

    const float* Ap = A + (row0 + arow) * K + ac8;
    const float* Wp = W + brow * N + col0 + bcol;

    float4 fa0 = *(const float4*)Ap;
    float4 fa1 = *(const float4*)(Ap + 4);
    float4 fb0 = *(const float4*)Wp;
    float4 fb1 = *(const float4*)(Wp + 4);

    for (int k0 = 0; k0 < K; k0 += 16) {
        As[ac8 + 0][arow] = fa0.x; As[ac8 + 1][arow] = fa0.y;
        As[ac8 + 2][arow] = fa0.z; As[ac8 + 3][arow] = fa0.w;
        As[ac8 + 4][arow] = fa1.x; As[ac8 + 5][arow] = fa1.y;
        As[ac8 + 6][arow] = fa1.z; As[ac8 + 7][arow] = fa1.w;
        *(float4*)&Bs[brow][bcol]     = fb0;
        *(float4*)&Bs[brow][bcol + 4] = fb1;
        __syncthreads();
        if (k0 + 16 < K) {
            fa0 = *(const float4*)(Ap + k0 + 16);
            fa1 = *(const float4*)(Ap + k0 + 20);
            fb0 = *(const float4*)(Wp + (k0 + 16) * N);
            fb1 = *(const float4*)(Wp + (k0 + 16) * N + 4);
        }
#pragma unroll
        for (int kk = 0; kk < 16; kk++) {
            float4 alo = *(const float4*)&As[kk][ty * 8];
            float4 ahi = *(const float4*)&As[kk][ty * 8 + 4];
            ulonglong2 bA = *(const ulonglong2*)&Bs[kk][tx * 8];
            ulonglong2 bB = *(const ulonglong2*)&Bs[kk][tx * 8 + 4];
            ull a2;
            a2 = dup2(alo.x); ff2(acc[0][0], a2, bA.x); ff2(acc[0][1], a2, bA.y); ff2(acc[0][2], a2, bB.x); ff2(acc[0][3], a2, bB.y);
            a2 = dup2(alo.y); ff2(acc[1][0], a2, bA.x); ff2(acc[1][1], a2, bA.y); ff2(acc[1][2], a2, bB.x); ff2(acc[1][3], a2, bB.y);
            a2 = dup2(alo.z); ff2(acc[2][0], a2, bA.x); ff2(acc[2][1], a2, bA.y); ff2(acc[2][2], a2, bB.x); ff2(acc[2][3], a2, bB.y);
            a2 = dup2(alo.w); ff2(acc[3][0], a2, bA.x); ff2(acc[3][1], a2, bA.y); ff2(acc[3][2], a2, bB.x); ff2(acc[3][3], a2, bB.y);
            a2 = dup2(ahi.x); ff2(acc[4][0], a2, bA.x); ff2(acc[4][1], a2, bA.y); ff2(acc[4][2], a2, bB.x); ff2(acc[4][3], a2, bB.y);
            a2 = dup2(ahi.y); ff2(acc[5][0], a2, bA.x); ff2(acc[5][1], a2, bA.y); ff2(acc[5][2], a2, bB.x); ff2(acc[5][3], a2, bB.y);
            a2 = dup2(ahi.z); ff2(acc[6][0], a2, bA.x); ff2(acc[6][1], a2, bA.y); ff2(acc[6][2], a2, bB.x); ff2(acc[6][3], a2, bB.y);
            a2 = dup2(ahi.w); ff2(acc[7][0], a2, bA.x); ff2(acc[7][1], a2, bA.y); ff2(acc[7][2], a2, bB.x); ff2(acc[7][3], a2, bB.y);
        }
        __syncthreads();
    }
}

// ---- quad projection GEMM: z=0:q(rope*0.125) 1:k(rope) 2:v 3:g(silu) ----
__global__ void __launch_bounds__(256, 2) qkvg_gemm(
    const float* __restrict__ A,
    const float* __restrict__ Wq_, const float* __restrict__ Wk_,
    const float* __restrict__ Wv_, const float* __restrict__ Wg_,
    const float* __restrict__ bq_, const float* __restrict__ bk_,
    const float* __restrict__ bv_, const float* __restrict__ bg_) {
    __shared__ float As[16][132];
    __shared__ float Bs[16][128];
    int z = blockIdx.z;
    const float* W    = (z == 0) ? Wq_ : (z == 1) ? Wk_ : (z == 2) ? Wv_ : Wg_;
    const float* bias = (z == 0) ? bq_ : (z == 1) ? bk_ : (z == 2) ? bv_ : bg_;
    float* out        = (z == 0) ? d_q : (z == 1) ? d_k : (z == 2) ? d_v : d_g;

    ull acc[8][4];
#pragma unroll
    for (int r = 0; r < 8; r++)
#pragma unroll
        for (int c = 0; c < 4; c++) acc[r][c] = 0ull;

    gemm128_accum<D, D>(A, W, As, Bs, acc);

    const int tid = threadIdx.x;
    const int tx = tid & 15, ty = tid >> 4;
    const int row0 = blockIdx.y * 128, col0 = blockIdx.x * 128;
#pragma unroll
    for (int r = 0; r < 8; r++) {
        int row = row0 + ty * 8 + r;
#pragma unroll
        for (int cp = 0; cp < 4; cp++) {
            int col = col0 + tx * 8 + 2 * cp;
            float2 vv = unpack2(acc[r][cp]);
            float v0 = vv.x + bias[col];
            float v1 = vv.y + bias[col + 1];
            float o0, o1;
            if (z <= 1) {
                int j = (col & 63) >> 1;
                float cc = d_cos[row * 32 + j];
                float sn = d_sin[row * 32 + j];
                float sc = (z == 0) ? 0.125f : 1.0f;
                o0 = (v0 * cc - v1 * sn) * sc;
                o1 = (v1 * cc + v0 * sn) * sc;
            } else if (z == 2) {
                o0 = v0; o1 = v1;
            } else {
                o0 = v0 / (1.0f + expf(-v0));
                o1 = v1 / (1.0f + expf(-v1));
            }
            *(float2*)&out[row * D + col] = make_float2(o0, o1);
        }
    }
}

// ---- FFN1 GEMM with SiLU: [S,512]@[512,2048] ----
__global__ void __launch_bounds__(256, 2) ffn1_gemm(
    const float* __restrict__ A, const float* __restrict__ W,
    const float* __restrict__ bias) {
    __shared__ float As[16][132];
    __shared__ float Bs[16][128];
    ull acc[8][4];
#pragma unroll
    for (int r = 0; r < 8; r++)
#pragma unroll
        for (int c = 0; c < 4; c++) acc[r][c] = 0ull;

    gemm128_accum<FF, D>(A, W, As, Bs, acc);

    const int tid = threadIdx.x;
    const int tx = tid & 15, ty = tid >> 4;
    const int row0 = blockIdx.y * 128, col0 = blockIdx.x * 128;
#pragma unroll
    for (int r = 0; r < 8; r++) {
        int row = row0 + ty * 8 + r;
#pragma unroll
        for (int cp = 0; cp < 4; cp++) {
            int col = col0 + tx * 8 + 2 * cp;
            float2 vv = unpack2(acc[r][cp]);
            float v0 = vv.x + bias[col];
            float v1 = vv.y + bias[col + 1];
            v0 = v0 / (1.0f + expf(-v0));
            v1 = v1 / (1.0f + expf(-v1));
            *(float2*)&d_ff[row * FF + col] = make_float2(v0, v1);
        }
    }
}

// ---- BM=64 BN=128 residual GEMM (N=512): C += A(*A2)@W + bias ----
template <int K, bool MULA>
__global__ void __launch_bounds__(256, 2) gemm64_res(
    const float* __restrict__ A, const float* __restrict__ A2,
    const float* __restrict__ W, const float* __restrict__ bias,
    float* __restrict__ C) {
    __shared__ float As[16][68];
    __shared__ float Bs[16][128];
    const int tid = threadIdx.x;
    const int row0 = blockIdx.y * 64;
    const int col0 = blockIdx.x * 128;
    const int arow = tid >> 2, ac4 = (tid & 3) * 4;
    const int brow = tid >> 4, bcol = (tid & 15) * 8;
    const int tx = tid & 15, ty = tid >> 4;

    const float* Ap  = A  + (row0 + arow) * K + ac4;
    const float* A2p = A2 + (row0 + arow) * K + ac4;
    const float* Wp  = W + brow * 512 + col0 + bcol;

    float4 fa = *(const float4*)Ap;
    if (MULA) {
        float4 fm = *(const float4*)A2p;
        fa.x *= fm.x; fa.y *= fm.y; fa.z *= fm.z; fa.w *= fm.w;
    }
    float4 fb0 = *(const float4*)Wp;
    float4 fb1 = *(const float4*)(Wp + 4);

    ull acc[4][4];
#pragma unroll
    for (int r = 0; r < 4; r++)
#pragma unroll
        for (int c = 0; c < 4; c++) acc[r][c] = 0ull;

    for (int k0 = 0; k0 < K; k0 += 16) {
        As[ac4 + 0][arow] = fa.x; As[ac4 + 1][arow] = fa.y;
        As[ac4 + 2][arow] = fa.z; As[ac4 + 3][arow] = fa.w;
        *(float4*)&Bs[brow][bcol]     = fb0;
        *(float4*)&Bs[brow][bcol + 4] = fb1;
        __syncthreads();
        if (k0 + 16 < K) {
            fa = *(const float4*)(Ap + k0 + 16);
            if (MULA) {
                float4 fm = *(const float4*)(A2p + k0 + 16);
                fa.x *= fm.x; fa.y *= fm.y; fa.z *= fm.z; fa.w *= fm.w;
            }
            fb0 = *(const float4*)(Wp + (k0 + 16) * 512);
            fb1 = *(const float4*)(Wp + (k0 + 16) * 512 + 4);
        }
#pragma unroll
        for (int kk = 0; kk < 16; kk++) {
            float4 av = *(const float4*)&As[kk][ty * 4];
            ulonglong2 bA = *(const ulonglong2*)&Bs[kk][tx * 8];
            ulonglong2 bB = *(const ulonglong2*)&Bs[kk][tx * 8 + 4];
            ull a2;
            a2 = dup2(av.x); ff2(acc[0][0], a2, bA.x); ff2(acc[0][1], a2, bA.y); ff2(acc[0][2], a2, bB.x); ff2(acc[0][3], a2, bB.y);
            a2 = dup2(av.y); ff2(acc[1][0], a2, bA.x); ff2(acc[1][1], a2, bA.y); ff2(acc[1][2], a2, bB.x); ff2(acc[1][3], a2, bB.y);
            a2 = dup2(av.z); ff2(acc[2][0], a2, bA.x); ff2(acc[2][1], a2, bA.y); ff2(acc[2][2], a2, bB.x); ff2(acc[2][3], a2, bB.y);
            a2 = dup2(av.w); ff2(acc[3][0], a2, bA.x); ff2(acc[3][1], a2, bA.y); ff2(acc[3][2], a2, bB.x); ff2(acc[3][3], a2, bB.y);
        }
        __syncthreads();
    }

#pragma unroll
    for (int r = 0; r < 4; r++) {
        int row = row0 + ty * 4 + r;
#pragma unroll
        for (int cp = 0; cp < 4; cp++) {
            int col = col0 + tx * 8 + 2 * cp;
            float2 vv = unpack2(acc[r][cp]);
            float2 oldv = *(float2*)&C[row * 512 + col];
            float o0 = vv.x + bias[col]     + oldv.x;
            float o1 = vv.y + bias[col + 1] + oldv.y;
            *(float2*)&C[row * 512 + col] = make_float2(o0, o1);
        }
    }
}

// ================= chunked retention =================
// R1: U[h][c] = sum_p gamma^(63-p) k_p (outer) v_p   (64x64 per chunk)
__global__ void chunk_kv_kernel(const float* __restrict__ k, const float* __restrict__ v) {
    __shared__ float ks[64][68];
    __shared__ float vs[64][68];
    int c = blockIdx.x, h = blockIdx.y;
    int s0 = c * 64;
    int tid = threadIdx.x;
    const float* gp = d_gpow + h * S;

    for (int i = tid; i < 64 * 16; i += 256) {
        int r = i >> 4;
        int c4 = (i & 15) * 4;
        float g = gp[63 - r];
        float4 kv = *(const float4*)&k[(s0 + r) * D + h * DH + c4];
        ks[r][c4 + 0] = kv.x * g; ks[r][c4 + 1] = kv.y * g;
        ks[r][c4 + 2] = kv.z * g; ks[r][c4 + 3] = kv.w * g;
        float4 vv = *(const float4*)&v[(s0 + r) * D + h * DH + c4];
        vs[r][c4 + 0] = vv.x; vs[r][c4 + 1] = vv.y;
        vs[r][c4 + 2] = vv.z; vs[r][c4 + 3] = vv.w;
    }
    __syncthreads();

    int tx = tid & 15, ty = tid >> 4;
    float acc[4][4] = {};
#pragma unroll 8
    for (int p = 0; p < 64; p++) {
        float4 a = *(const float4*)&ks[p][ty * 4];
        float4 b = *(const float4*)&vs[p][tx * 4];
        acc[0][0] += a.x * b.x; acc[0][1] += a.x * b.y; acc[0][2] += a.x * b.z; acc[0][3] += a.x * b.w;
        acc[1][0] += a.y * b.x; acc[1][1] += a.y * b.y; acc[1][2] += a.y * b.z; acc[1][3] += a.y * b.w;
        acc[2][0] += a.z * b.x; acc[2][1] += a.z * b.y; acc[2][2] += a.z * b.z; acc[2][3] += a.z * b.w;
        acc[3][0] += a.w * b.x; acc[3][1] += a.w * b.y; acc[3][2] += a.w * b.z; acc[3][3] += a.w * b.w;
    }
    float* U = d_U + (h * NC + c) * (DH * DH);
#pragma unroll
    for (int r = 0; r < 4; r++)
        *(float4*)&U[(ty * 4 + r) * DH + tx * 4] = make_float4(acc[r][0], acc[r][1], acc[r][2], acc[r][3]);
}

// R2: parallel-over-elements scan over chunks: M[c] = gamma^64 * M[c-1] + U[c-1]
__global__ void scan_kernel() {
    int e = blockIdx.x * blockDim.x + threadIdx.x;   // H*4096
    if (e >= H * DH * DH) return;
    int h = e >> 12;
    int idx = e & 4095;
    float gc = d_gpow[h * S + 64];
    float m = 0.0f;
    for (int c = 0; c < NC; c++) {
        d_M[(h * NC + c) * 4096 + idx] = m;
        m = gc * m + d_U[(h * NC + c) * 4096 + idx];
    }
}

// R3: intra-chunk masked attention + cross term + groupnorm
__global__ void retn_kernel(const float* __restrict__ q, const float* __restrict__ k,
                            const float* __restrict__ v, float* __restrict__ ret) {
    __shared__ float qs[64][65];
    __shared__ float ks[32][65];
    __shared__ float vs[32][65];
    __shared__ float ss[64][33];

    int h = blockIdx.y;
    int cidx = blockIdx.x;
    int s0 = cidx * 64;
    int tid = threadIdx.x;

    for (int i = tid; i < 64 * 16; i += 256) {
        int r = i >> 4;
        int c4 = (i & 15) * 4;
        float4 t = *(const float4*)&q[(s0 + r) * D + h * DH + c4];
        qs[r][c4 + 0] = t.x; qs[r][c4 + 1] = t.y; qs[r][c4 + 2] = t.z; qs[r][c4 + 3] = t.w;
    }

    int aty = tid >> 4, atx = tid & 15;
    int bty = tid >> 4, btx = tid & 15;
    float acc[4][4] = {};
    const float* gp = d_gpow + h * S;
    const float* Mh = d_M + (h * NC + cidx) * (DH * DH);
    __syncthreads();

    // ---- intra-chunk: 2 key tiles of 32 ----
    for (int t = 0; t < 2; t++) {
        int m0 = s0 + t * 32;
        for (int i = tid; i < 32 * 16; i += 256) {
            int r = i >> 4;
            int c4 = (i & 15) * 4;
            float4 kv = *(const float4*)&k[(m0 + r) * D + h * DH + c4];
            ks[r][c4 + 0] = kv.x; ks[r][c4 + 1] = kv.y; ks[r][c4 + 2] = kv.z; ks[r][c4 + 3] = kv.w;
            float4 vv = *(const float4*)&v[(m0 + r) * D + h * DH + c4];
            vs[r][c4 + 0] = vv.x; vs[r][c4 + 1] = vv.y; vs[r][c4 + 2] = vv.z; vs[r][c4 + 3] = vv.w;
        }
        __syncthreads();

        float sv[4][2] = {};
#pragma unroll 16
        for (int d = 0; d < 64; d++) {
            float qr0 = qs[aty * 4 + 0][d];
            float qr1 = qs[aty * 4 + 1][d];
            float qr2 = qs[aty * 4 + 2][d];
            float qr3 = qs[aty * 4 + 3][d];
            float kc0 = ks[atx * 2 + 0][d];
            float kc1 = ks[atx * 2 + 1][d];
            sv[0][0] += qr0 * kc0; sv[0][1] += qr0 * kc1;
            sv[1][0] += qr1 * kc0; sv[1][1] += qr1 * kc1;
            sv[2][0] += qr2 * kc0; sv[2][1] += qr2 * kc1;
            sv[3][0] += qr3 * kc0; sv[3][1] += qr3 * kc1;
        }
#pragma unroll
        for (int r = 0; r < 4; r++)
#pragma unroll
            for (int c = 0; c < 2; c++) {
                int qi = s0 + aty * 4 + r;
                int kj = m0 + atx * 2 + c;
                int dist = qi - kj;
                ss[aty * 4 + r][atx * 2 + c] = (dist >= 0) ? sv[r][c] * gp[dist] : 0.0f;
            }
        __syncthreads();

#pragma unroll 8
        for (int j = 0; j < 32; j++) {
            float vr0 = vs[j][btx * 4 + 0];
            float vr1 = vs[j][btx * 4 + 1];
            float vr2 = vs[j][btx * 4 + 2];
            float vr3 = vs[j][btx * 4 + 3];
            float s0r = ss[bty * 4 + 0][j];
            float s1r = ss[bty * 4 + 1][j];
            float s2r = ss[bty * 4 + 2][j];
            float s3r = ss[bty * 4 + 3][j];
            acc[0][0] += s0r * vr0; acc[0][1] += s0r * vr1; acc[0][2] += s0r * vr2; acc[0][3] += s0r * vr3;
            acc[1][0] += s1r * vr0; acc[1][1] += s1r * vr1; acc[1][2] += s1r * vr2; acc[1][3] += s1r * vr3;
            acc[2][0] += s2r * vr0; acc[2][1] += s2r * vr1; acc[2][2] += s2r * vr2; acc[2][3] += s2r * vr3;
            acc[3][0] += s3r * vr0; acc[3][1] += s3r * vr1; acc[3][2] += s3r * vr2; acc[3][3] += s3r * vr3;
        }
        __syncthreads();
    }

    // ---- cross-chunk: ret += (gamma^(i+1) q_i) @ M ----
    if (cidx > 0) {
        for (int t2 = 0; t2 < 2; t2++) {
            for (int i = tid; i < 32 * 16; i += 256) {
                int r = i >> 4;
                int c4 = (i & 15) * 4;
                float4 mv = *(const float4*)&Mh[(t2 * 32 + r) * DH + c4];
                vs[r][c4 + 0] = mv.x; vs[r][c4 + 1] = mv.y; vs[r][c4 + 2] = mv.z; vs[r][c4 + 3] = mv.w;
            }
            for (int i = tid; i < 64 * 32; i += 256) {
                int r = i >> 5;
                int j = i & 31;
                ss[r][j] = qs[r][t2 * 32 + j] * gp[r + 1];
            }
            __syncthreads();
#pragma unroll 8
            for (int j = 0; j < 32; j++) {
                float vr0 = vs[j][btx * 4 + 0];
                float vr1 = vs[j][btx * 4 + 1];
                float vr2 = vs[j][btx * 4 + 2];
                float vr3 = vs[j][btx * 4 + 3];
                float s0r = ss[bty * 4 + 0][j];
                float s1r = ss[bty * 4 + 1][j];
                float s2r = ss[bty * 4 + 2][j];
                float s3r = ss[bty * 4 + 3][j];
                acc[0][0] += s0r * vr0; acc[0][1] += s0r * vr1; acc[0][2] += s0r * vr2; acc[0][3] += s0r * vr3;
                acc[1][0] += s1r * vr0; acc[1][1] += s1r * vr1; acc[1][2] += s1r * vr2; acc[1][3] += s1r * vr3;
                acc[2][0] += s2r * vr0; acc[2][1] += s2r * vr1; acc[2][2] += s2r * vr2; acc[2][3] += s2r * vr3;
                acc[3][0] += s3r * vr0; acc[3][1] += s3r * vr1; acc[3][2] += s3r * vr2; acc[3][3] += s3r * vr3;
            }
            __syncthreads();
        }
    }

    // ---- groupnorm over DH, write ----
#pragma unroll
    for (int r = 0; r < 4; r++)
#pragma unroll
        for (int c = 0; c < 4; c++)
            qs[bty * 4 + r][btx * 4 + c] = acc[r][c];
    __syncthreads();

    if (tid < 64) {
        int i = tid;
        float mu = 0.0f;
#pragma unroll 16
        for (int d = 0; d < 64; d++) mu += qs[i][d];
        mu *= (1.0f / 64.0f);
        float var = 0.0f;
#pragma unroll 16
        for (int d = 0; d < 64; d++) {
            float dd = qs[i][d] - mu;
            var += dd * dd;
        }
        var *= (1.0f / 64.0f);
        float rs = rsqrtf(var + 1e-6f);
#pragma unroll 16
        for (int d = 0; d < 64; d++)
            ret[(s0 + i) * D + h * DH + d] = (qs[i][d] - mu) * rs;
    }
}

// ---------------- final: out[s] = sigmoid(x[s,:] . Wout + bout) ----------------
__global__ void final_kernel(const float* __restrict__ Wout, const float* __restrict__ bout,
                             float* __restrict__ out) {
    int row = blockIdx.x;
    int t = threadIdx.x;   // 64
    float s = 0.0f;
    for (int i = t; i < D; i += 64) s += d_x[row * D + i] * Wout[i];
    __shared__ float red[64];
    red[t] = s;
    __syncthreads();
    for (int o = 32; o > 0; o >>= 1) {
        if (t < o) red[t] += red[t + o];
        __syncthreads();
    }
    if (t == 0) out[row] = 1.0f / (1.0f + expf(-(red[0] + bout[0])));
}

// ---------------- host orchestration ----------------
extern "C" void kernel_launch(void* const* d_in, const int* in_sizes, int n_in,
                              void* d_out, int out_size) {
    const float* x_in  = (const float*)d_in[0];
    const float* pe    = (const float*)d_in[1];
    const float* Wq    = (const float*)d_in[2];
    const float* bq    = (const float*)d_in[3];
    const float* Wk    = (const float*)d_in[4];
    const float* bk    = (const float*)d_in[5];
    const float* Wv    = (const float*)d_in[6];
    const float* bv    = (const float*)d_in[7];
    const float* Wg    = (const float*)d_in[8];
    const float* bg    = (const float*)d_in[9];
    const float* Wo    = (const float*)d_in[10];
    const float* bo    = (const float*)d_in[11];
    const float* ln1w  = (const float*)d_in[12];
    const float* ln1b  = (const float*)d_in[13];
    const float* ln2w  = (const float*)d_in[14];
    const float* ln2b  = (const float*)d_in[15];
    const float* W1    = (const float*)d_in[16];
    const float* b1    = (const float*)d_in[17];
    const float* W2    = (const float*)d_in[18];
    const float* b2    = (const float*)d_in[19];
    const float* Wout  = (const float*)d_in[20];
    const float* bout  = (const float*)d_in[21];
    float* out = (float*)d_out;

    void *px_, *py_, *pq_, *pk_, *pv_, *pg_, *pret_, *pff_;
    cudaGetSymbolAddress(&px_,  d_x);
    cudaGetSymbolAddress(&py_,  d_y);
    cudaGetSymbolAddress(&pq_,  d_q);
    cudaGetSymbolAddress(&pk_,  d_k);
    cudaGetSymbolAddress(&pv_,  d_v);
    cudaGetSymbolAddress(&pg_,  d_g);
    cudaGetSymbolAddress(&pret_, d_ret);
    cudaGetSymbolAddress(&pff_, d_ff);
    float* px   = (float*)px_;
    float* py   = (float*)py_;
    float* pq   = (float*)pq_;
    float* pk   = (float*)pk_;
    float* pv   = (float*)pv_;
    float* pg   = (float*)pg_;
    float* pret = (float*)pret_;
    float* pff  = (float*)pff_;

    init_tables_kernel<<<(S * 32 + 255) / 256, 256>>>();
    add_pos_kernel<<<(S * D + 255) / 256, 256>>>(x_in, pe);

    dim3 grid_qkvg(D / 128, S / 128, 4);     // (4,16,4) = 256 blocks
    dim3 grid_ff1(FF / 128, S / 128);        // (16,16)  = 256 blocks
    dim3 grid_64(D / 128, S / 64);           // (4,32)   = 128 blocks
    dim3 grid_ret(NC, H);                    // (32,8)   = 256 blocks

    for (int l = 0; l < L; l++) {
        layernorm_kernel<<<S, 256>>>(px, ln1w + l * D, ln1b + l * D, py, 1e-5f);

        qkvg_gemm<<<grid_qkvg, 256>>>(py,
            Wq + l * D * D, Wk + l * D * D, Wv + l * D * D, Wg + l * D * D,
            bq + l * D, bk + l * D, bv + l * D, bg + l * D);

        chunk_kv_kernel<<<grid_ret, 256>>>(pk, pv);
        scan_kernel<<<(H * DH * DH + 255) / 256, 256>>>();
        retn_kernel<<<grid_ret, 256>>>(pq, pk, pv, pret);

        // x += (g*ret) @ Wo + bo   (A-side elementwise product fused)
        gemm64_res<D, true><<<grid_64, 256>>>(pg, pret, Wo + l * D * D, bo + l * D, px);

        layernorm_kernel<<<S, 256>>>(px, ln2w + l * D, ln2b + l * D, py, 1e-5f);
        ffn1_gemm<<<grid_ff1, 256>>>(py, W1 + l * D * FF, b1 + l * FF);
        gemm64_res<FF, false><<<grid_64, 256>>>(pff, pff, W2 + l * FF * D, b2 + l * D, px);
    }

    final_kernel<<<S, 64>>>(Wout, bout, out);
}

// round 10
// speedup vs baseline: 1.9787x; 1.2122x over previous
#include <cuda_runtime.h>
#include <math.h>

#define S 2048
#define D 512
#define H 8
#define DH 64
#define L 4
#define FF 2048
#define NC (S / 64)          // 32 chunks of 64

typedef unsigned long long ull;

// ---------------- scratch (static device globals; no allocation) ----------------
__device__ float d_x  [S * D];
__device__ float d_y  [S * D];
__device__ float d_q  [S * D];
__device__ float d_k  [S * D];
__device__ float d_v  [S * D];
__device__ float d_g  [S * D];
__device__ float d_ret[S * D];
__device__ float d_ff [S * FF];
__device__ float d_sin[S * (DH / 2)];
__device__ float d_cos[S * (DH / 2)];
__device__ float d_gpow[H * S];
__device__ float d_U[H * NC * DH * DH];   // per-chunk decayed k^T v
__device__ float d_M[H * NC * DH * DH];   // prefix states

// ---------------- f32x2 helpers ----------------
__device__ __forceinline__ ull dup2(float x) {
    ull r; asm("mov.b64 %0, {%1, %1};" : "=l"(r) : "f"(x)); return r;
}
__device__ __forceinline__ void ff2(ull& d, ull a, ull b) {
    asm("fma.rn.f32x2 %0, %1, %2, %0;" : "+l"(d) : "l"(a), "l"(b));
}
__device__ __forceinline__ float2 unpack2(ull p) {
    float2 r; asm("mov.b64 {%0, %1}, %2;" : "=f"(r.x), "=f"(r.y) : "l"(p)); return r;
}

// ---------------- setup tables (double precision, matches numpy float64) --------
__global__ void init_tables_kernel() {
    int idx = blockIdx.x * blockDim.x + threadIdx.x;
    if (idx < S * (DH / 2)) {
        int s = idx / (DH / 2);
        int j = idx % (DH / 2);
        double theta = pow(10000.0, -(double)(2 * j) / (double)DH);
        double ang = (double)s * theta;
        d_sin[idx] = (float)sin(ang);
        d_cos[idx] = (float)cos(ang);
    }
    if (idx < H * S) {
        int h = idx / S;
        int dd = idx % S;
        double lg0 = log(1.0 / 32.0);
        double lg1 = log(1.0 / 512.0);
        double gamma = 1.0 - exp(lg0 + (lg1 - lg0) * (double)h / 7.0);
        d_gpow[idx] = (float)exp((double)dd * log(gamma));
    }
}

__global__ void add_pos_kernel(const float* __restrict__ x, const float* __restrict__ pe) {
    int i = blockIdx.x * blockDim.x + threadIdx.x;
    if (i < S * D) d_x[i] = x[i] + pe[i % D];
}

// ---------------- layernorm ----------------
__global__ void layernorm_kernel(const float* __restrict__ in,
                                 const float* __restrict__ w,
                                 const float* __restrict__ b,
                                 float* __restrict__ out, float eps) {
    int row = blockIdx.x;
    int t = threadIdx.x;
    const float* xr = in + row * D;
    __shared__ float red[256];

    float v0 = xr[t];
    float v1 = xr[t + 256];
    red[t] = v0 + v1;
    __syncthreads();
    for (int o = 128; o > 0; o >>= 1) {
        if (t < o) red[t] += red[t + o];
        __syncthreads();
    }
    float mu = red[0] * (1.0f / D);
    __syncthreads();
    float a0 = v0 - mu, a1 = v1 - mu;
    red[t] = a0 * a0 + a1 * a1;
    __syncthreads();
    for (int o = 128; o > 0; o >>= 1) {
        if (t < o) red[t] += red[t + o];
        __syncthreads();
    }
    float rstd = rsqrtf(red[0] * (1.0f / D) + eps);
    out[row * D + t]       = a0 * rstd * w[t]       + b[t];
    out[row * D + t + 256] = a1 * rstd * w[t + 256] + b[t + 256];
}

// ================= f32x2 GEMM core: BM=128, BN=128, BK=16, 256 thr ==============
// Warp tiling: 8 warps as 4x2 (32 rows x 64 cols each); lanes 4x8 (8 rows x 8 cols).
// Double-buffered smem, one sync per k-tile.
template <int N, int K>
__device__ __forceinline__ void gemm128_accum(const float* __restrict__ A,
                                              const float* __restrict__ W,
                                              float (*As)[16][132], float (*Bs)[16][128],
                                              ull (&acc)[8][4]) {
    const int tid = threadIdx.x;
    const int row0 = blockIdx.y * 128;
    const int col0 = blockIdx.x * 128;
    const int arow = tid >> 1, ac8 = (tid & 1) * 8;
    const int brow = tid >> 4, bcol = (tid & 15) * 8;
    const int warp = tid >> 5, lane = tid & 31;
    const int ro = (warp >> 1) * 32 + (lane >> 3) * 8;
    const int co = (warp & 1) * 64 + (lane & 7) * 8;

    const float* Ap = A + (row0 + arow) * K + ac8;
    const float* Wp = W + brow * N + col0 + bcol;

    float4 fa0 = *(const float4*)Ap;
    float4 fa1 = *(const float4*)(Ap + 4);
    float4 fb0 = *(const float4*)Wp;
    float4 fb1 = *(const float4*)(Wp + 4);

    int buf = 0;
    As[0][ac8 + 0][arow] = fa0.x; As[0][ac8 + 1][arow] = fa0.y;
    As[0][ac8 + 2][arow] = fa0.z; As[0][ac8 + 3][arow] = fa0.w;
    As[0][ac8 + 4][arow] = fa1.x; As[0][ac8 + 5][arow] = fa1.y;
    As[0][ac8 + 6][arow] = fa1.z; As[0][ac8 + 7][arow] = fa1.w;
    *(float4*)&Bs[0][brow][bcol]     = fb0;
    *(float4*)&Bs[0][brow][bcol + 4] = fb1;
    __syncthreads();

    for (int k0 = 0; k0 < K; k0 += 16) {
        bool more = (k0 + 16 < K);
        if (more) {
            fa0 = *(const float4*)(Ap + k0 + 16);
            fa1 = *(const float4*)(Ap + k0 + 20);
            fb0 = *(const float4*)(Wp + (k0 + 16) * N);
            fb1 = *(const float4*)(Wp + (k0 + 16) * N + 4);
        }
#pragma unroll
        for (int kk = 0; kk < 16; kk++) {
            float4 alo = *(const float4*)&As[buf][kk][ro];
            float4 ahi = *(const float4*)&As[buf][kk][ro + 4];
            ulonglong2 bA = *(const ulonglong2*)&Bs[buf][kk][co];
            ulonglong2 bB = *(const ulonglong2*)&Bs[buf][kk][co + 4];
            ull a2;
            a2 = dup2(alo.x); ff2(acc[0][0], a2, bA.x); ff2(acc[0][1], a2, bA.y); ff2(acc[0][2], a2, bB.x); ff2(acc[0][3], a2, bB.y);
            a2 = dup2(alo.y); ff2(acc[1][0], a2, bA.x); ff2(acc[1][1], a2, bA.y); ff2(acc[1][2], a2, bB.x); ff2(acc[1][3], a2, bB.y);
            a2 = dup2(alo.z); ff2(acc[2][0], a2, bA.x); ff2(acc[2][1], a2, bA.y); ff2(acc[2][2], a2, bB.x); ff2(acc[2][3], a2, bB.y);
            a2 = dup2(alo.w); ff2(acc[3][0], a2, bA.x); ff2(acc[3][1], a2, bA.y); ff2(acc[3][2], a2, bB.x); ff2(acc[3][3], a2, bB.y);
            a2 = dup2(ahi.x); ff2(acc[4][0], a2, bA.x); ff2(acc[4][1], a2, bA.y); ff2(acc[4][2], a2, bB.x); ff2(acc[4][3], a2, bB.y);
            a2 = dup2(ahi.y); ff2(acc[5][0], a2, bA.x); ff2(acc[5][1], a2, bA.y); ff2(acc[5][2], a2, bB.x); ff2(acc[5][3], a2, bB.y);
            a2 = dup2(ahi.z); ff2(acc[6][0], a2, bA.x); ff2(acc[6][1], a2, bA.y); ff2(acc[6][2], a2, bB.x); ff2(acc[6][3], a2, bB.y);
            a2 = dup2(ahi.w); ff2(acc[7][0], a2, bA.x); ff2(acc[7][1], a2, bA.y); ff2(acc[7][2], a2, bB.x); ff2(acc[7][3], a2, bB.y);
        }
        if (more) {
            int nb = buf ^ 1;
            As[nb][ac8 + 0][arow] = fa0.x; As[nb][ac8 + 1][arow] = fa0.y;
            As[nb][ac8 + 2][arow] = fa0.z; As[nb][ac8 + 3][arow] = fa0.w;
            As[nb][ac8 + 4][arow] = fa1.x; As[nb][ac8 + 5][arow] = fa1.y;
            As[nb][ac8 + 6][arow] = fa1.z; As[nb][ac8 + 7][arow] = fa1.w;
            *(float4*)&Bs[nb][brow][bcol]     = fb0;
            *(float4*)&Bs[nb][brow][bcol + 4] = fb1;
            __syncthreads();
            buf = nb;
        }
    }
}

// ---- quad projection GEMM: z=0:q(rope*0.125) 1:k(rope) 2:v 3:g(silu) ----
__global__ void __launch_bounds__(256, 2) qkvg_gemm(
    const float* __restrict__ A,
    const float* __restrict__ Wq_, const float* __restrict__ Wk_,
    const float* __restrict__ Wv_, const float* __restrict__ Wg_,
    const float* __restrict__ bq_, const float* __restrict__ bk_,
    const float* __restrict__ bv_, const float* __restrict__ bg_) {
    __shared__ float As[2][16][132];
    __shared__ float Bs[2][16][128];
    int z = blockIdx.z;
    const float* W    = (z == 0) ? Wq_ : (z == 1) ? Wk_ : (z == 2) ? Wv_ : Wg_;
    const float* bias = (z == 0) ? bq_ : (z == 1) ? bk_ : (z == 2) ? bv_ : bg_;
    float* out        = (z == 0) ? d_q : (z == 1) ? d_k : (z == 2) ? d_v : d_g;

    ull acc[8][4];
#pragma unroll
    for (int r = 0; r < 8; r++)
#pragma unroll
        for (int c = 0; c < 4; c++) acc[r][c] = 0ull;

    gemm128_accum<D, D>(A, W, As, Bs, acc);

    const int tid = threadIdx.x;
    const int warp = tid >> 5, lane = tid & 31;
    const int ro = (warp >> 1) * 32 + (lane >> 3) * 8;
    const int co = (warp & 1) * 64 + (lane & 7) * 8;
    const int row0 = blockIdx.y * 128, col0 = blockIdx.x * 128;
#pragma unroll
    for (int r = 0; r < 8; r++) {
        int row = row0 + ro + r;
#pragma unroll
        for (int half = 0; half < 2; half++) {
            int col = col0 + co + 4 * half;
            float2 p0 = unpack2(acc[r][2 * half]);
            float2 p1 = unpack2(acc[r][2 * half + 1]);
            float v0 = p0.x + bias[col];
            float v1 = p0.y + bias[col + 1];
            float v2 = p1.x + bias[col + 2];
            float v3 = p1.y + bias[col + 3];
            float4 o;
            if (z <= 1) {
                int j = (col & 63) >> 1;
                float c0 = d_cos[row * 32 + j],     s0 = d_sin[row * 32 + j];
                float c1 = d_cos[row * 32 + j + 1], s1 = d_sin[row * 32 + j + 1];
                float sc = (z == 0) ? 0.125f : 1.0f;
                o.x = (v0 * c0 - v1 * s0) * sc;
                o.y = (v1 * c0 + v0 * s0) * sc;
                o.z = (v2 * c1 - v3 * s1) * sc;
                o.w = (v3 * c1 + v2 * s1) * sc;
            } else if (z == 2) {
                o = make_float4(v0, v1, v2, v3);
            } else {
                o.x = v0 / (1.0f + expf(-v0));
                o.y = v1 / (1.0f + expf(-v1));
                o.z = v2 / (1.0f + expf(-v2));
                o.w = v3 / (1.0f + expf(-v3));
            }
            *(float4*)&out[row * D + col] = o;
        }
    }
}

// ---- FFN1 GEMM with SiLU: [S,512]@[512,2048] ----
__global__ void __launch_bounds__(256, 2) ffn1_gemm(
    const float* __restrict__ A, const float* __restrict__ W,
    const float* __restrict__ bias) {
    __shared__ float As[2][16][132];
    __shared__ float Bs[2][16][128];
    ull acc[8][4];
#pragma unroll
    for (int r = 0; r < 8; r++)
#pragma unroll
        for (int c = 0; c < 4; c++) acc[r][c] = 0ull;

    gemm128_accum<FF, D>(A, W, As, Bs, acc);

    const int tid = threadIdx.x;
    const int warp = tid >> 5, lane = tid & 31;
    const int ro = (warp >> 1) * 32 + (lane >> 3) * 8;
    const int co = (warp & 1) * 64 + (lane & 7) * 8;
    const int row0 = blockIdx.y * 128, col0 = blockIdx.x * 128;
#pragma unroll
    for (int r = 0; r < 8; r++) {
        int row = row0 + ro + r;
#pragma unroll
        for (int half = 0; half < 2; half++) {
            int col = col0 + co + 4 * half;
            float2 p0 = unpack2(acc[r][2 * half]);
            float2 p1 = unpack2(acc[r][2 * half + 1]);
            float v0 = p0.x + bias[col];
            float v1 = p0.y + bias[col + 1];
            float v2 = p1.x + bias[col + 2];
            float v3 = p1.y + bias[col + 3];
            float4 o;
            o.x = v0 / (1.0f + expf(-v0));
            o.y = v1 / (1.0f + expf(-v1));
            o.z = v2 / (1.0f + expf(-v2));
            o.w = v3 / (1.0f + expf(-v3));
            *(float4*)&d_ff[row * FF + col] = o;
        }
    }
}

// ---- BM=64 BN=128 residual GEMM (N=512): C += A(*A2)@W + bias ----
// Warp tiling: 8 warps as 2x4 (32 rows x 32 cols); lanes 8x4 (4 rows x 8 cols).
template <int K, bool MULA>
__global__ void __launch_bounds__(256, 2) gemm64_res(
    const float* __restrict__ A, const float* __restrict__ A2,
    const float* __restrict__ W, const float* __restrict__ bias,
    float* __restrict__ C) {
    __shared__ float As[2][16][68];
    __shared__ float Bs[2][16][128];
    const int tid = threadIdx.x;
    const int row0 = blockIdx.y * 64;
    const int col0 = blockIdx.x * 128;
    const int arow = tid >> 2, ac4 = (tid & 3) * 4;
    const int brow = tid >> 4, bcol = (tid & 15) * 8;
    const int warp = tid >> 5, lane = tid & 31;
    const int ro = (warp >> 2) * 32 + (lane >> 2) * 4;
    const int co = (warp & 3) * 32 + (lane & 3) * 8;

    const float* Ap  = A  + (row0 + arow) * K + ac4;
    const float* A2p = A2 + (row0 + arow) * K + ac4;
    const float* Wp  = W + brow * 512 + col0 + bcol;

    float4 fa = *(const float4*)Ap;
    if (MULA) {
        float4 fm = *(const float4*)A2p;
        fa.x *= fm.x; fa.y *= fm.y; fa.z *= fm.z; fa.w *= fm.w;
    }
    float4 fb0 = *(const float4*)Wp;
    float4 fb1 = *(const float4*)(Wp + 4);

    ull acc[4][4];
#pragma unroll
    for (int r = 0; r < 4; r++)
#pragma unroll
        for (int c = 0; c < 4; c++) acc[r][c] = 0ull;

    int buf = 0;
    As[0][ac4 + 0][arow] = fa.x; As[0][ac4 + 1][arow] = fa.y;
    As[0][ac4 + 2][arow] = fa.z; As[0][ac4 + 3][arow] = fa.w;
    *(float4*)&Bs[0][brow][bcol]     = fb0;
    *(float4*)&Bs[0][brow][bcol + 4] = fb1;
    __syncthreads();

    for (int k0 = 0; k0 < K; k0 += 16) {
        bool more = (k0 + 16 < K);
        if (more) {
            fa = *(const float4*)(Ap + k0 + 16);
            if (MULA) {
                float4 fm = *(const float4*)(A2p + k0 + 16);
                fa.x *= fm.x; fa.y *= fm.y; fa.z *= fm.z; fa.w *= fm.w;
            }
            fb0 = *(const float4*)(Wp + (k0 + 16) * 512);
            fb1 = *(const float4*)(Wp + (k0 + 16) * 512 + 4);
        }
#pragma unroll
        for (int kk = 0; kk < 16; kk++) {
            float4 av = *(const float4*)&As[buf][kk][ro];
            ulonglong2 bA = *(const ulonglong2*)&Bs[buf][kk][co];
            ulonglong2 bB = *(const ulonglong2*)&Bs[buf][kk][co + 4];
            ull a2;
            a2 = dup2(av.x); ff2(acc[0][0], a2, bA.x); ff2(acc[0][1], a2, bA.y); ff2(acc[0][2], a2, bB.x); ff2(acc[0][3], a2, bB.y);
            a2 = dup2(av.y); ff2(acc[1][0], a2, bA.x); ff2(acc[1][1], a2, bA.y); ff2(acc[1][2], a2, bB.x); ff2(acc[1][3], a2, bB.y);
            a2 = dup2(av.z); ff2(acc[2][0], a2, bA.x); ff2(acc[2][1], a2, bA.y); ff2(acc[2][2], a2, bB.x); ff2(acc[2][3], a2, bB.y);
            a2 = dup2(av.w); ff2(acc[3][0], a2, bA.x); ff2(acc[3][1], a2, bA.y); ff2(acc[3][2], a2, bB.x); ff2(acc[3][3], a2, bB.y);
        }
        if (more) {
            int nb = buf ^ 1;
            As[nb][ac4 + 0][arow] = fa.x; As[nb][ac4 + 1][arow] = fa.y;
            As[nb][ac4 + 2][arow] = fa.z; As[nb][ac4 + 3][arow] = fa.w;
            *(float4*)&Bs[nb][brow][bcol]     = fb0;
            *(float4*)&Bs[nb][brow][bcol + 4] = fb1;
            __syncthreads();
            buf = nb;
        }
    }

#pragma unroll
    for (int r = 0; r < 4; r++) {
        int row = row0 + ro + r;
#pragma unroll
        for (int half = 0; half < 2; half++) {
            int col = col0 + co + 4 * half;
            float2 p0 = unpack2(acc[r][2 * half]);
            float2 p1 = unpack2(acc[r][2 * half + 1]);
            float4 oldv = *(float4*)&C[row * 512 + col];
            float4 o;
            o.x = p0.x + bias[col]     + oldv.x;
            o.y = p0.y + bias[col + 1] + oldv.y;
            o.z = p1.x + bias[col + 2] + oldv.z;
            o.w = p1.y + bias[col + 3] + oldv.w;
            *(float4*)&C[row * 512 + col] = o;
        }
    }
}

// ================= chunked retention =================
// R1: U[h][c] = sum_p gamma^(63-p) k_p (outer) v_p   (64x64 per chunk)
__global__ void chunk_kv_kernel(const float* __restrict__ k, const float* __restrict__ v) {
    __shared__ float ks[64][68];
    __shared__ float vs[64][68];
    int c = blockIdx.x, h = blockIdx.y;
    int s0 = c * 64;
    int tid = threadIdx.x;
    const float* gp = d_gpow + h * S;

    for (int i = tid; i < 64 * 16; i += 256) {
        int r = i >> 4;
        int c4 = (i & 15) * 4;
        float g = gp[63 - r];
        float4 kv = *(const float4*)&k[(s0 + r) * D + h * DH + c4];
        ks[r][c4 + 0] = kv.x * g; ks[r][c4 + 1] = kv.y * g;
        ks[r][c4 + 2] = kv.z * g; ks[r][c4 + 3] = kv.w * g;
        float4 vv = *(const float4*)&v[(s0 + r) * D + h * DH + c4];
        vs[r][c4 + 0] = vv.x; vs[r][c4 + 1] = vv.y;
        vs[r][c4 + 2] = vv.z; vs[r][c4 + 3] = vv.w;
    }
    __syncthreads();

    int tx = tid & 15, ty = tid >> 4;
    float acc[4][4] = {};
#pragma unroll 8
    for (int p = 0; p < 64; p++) {
        float4 a = *(const float4*)&ks[p][ty * 4];
        float4 b = *(const float4*)&vs[p][tx * 4];
        acc[0][0] += a.x * b.x; acc[0][1] += a.x * b.y; acc[0][2] += a.x * b.z; acc[0][3] += a.x * b.w;
        acc[1][0] += a.y * b.x; acc[1][1] += a.y * b.y; acc[1][2] += a.y * b.z; acc[1][3] += a.y * b.w;
        acc[2][0] += a.z * b.x; acc[2][1] += a.z * b.y; acc[2][2] += a.z * b.z; acc[2][3] += a.z * b.w;
        acc[3][0] += a.w * b.x; acc[3][1] += a.w * b.y; acc[3][2] += a.w * b.z; acc[3][3] += a.w * b.w;
    }
    float* U = d_U + (h * NC + c) * (DH * DH);
#pragma unroll
    for (int r = 0; r < 4; r++)
        *(float4*)&U[(ty * 4 + r) * DH + tx * 4] = make_float4(acc[r][0], acc[r][1], acc[r][2], acc[r][3]);
}

// R2: parallel-over-elements scan over chunks: M[c] = gamma^64 * M[c-1] + U[c-1]
__global__ void scan_kernel() {
    int e = blockIdx.x * blockDim.x + threadIdx.x;   // H*4096
    if (e >= H * DH * DH) return;
    int h = e >> 12;
    int idx = e & 4095;
    float gc = d_gpow[h * S + 64];
    float m = 0.0f;
    for (int c = 0; c < NC; c++) {
        d_M[(h * NC + c) * 4096 + idx] = m;
        m = gc * m + d_U[(h * NC + c) * 4096 + idx];
    }
}

// R3: intra-chunk masked attention + cross term + groupnorm
__global__ void retn_kernel(const float* __restrict__ q, const float* __restrict__ k,
                            const float* __restrict__ v, float* __restrict__ ret) {
    __shared__ float qs[64][65];
    __shared__ float ks[32][65];
    __shared__ float vs[32][65];
    __shared__ float ss[64][33];

    int h = blockIdx.y;
    int cidx = blockIdx.x;
    int s0 = cidx * 64;
    int tid = threadIdx.x;

    for (int i = tid; i < 64 * 16; i += 256) {
        int r = i >> 4;
        int c4 = (i & 15) * 4;
        float4 t = *(const float4*)&q[(s0 + r) * D + h * DH + c4];
        qs[r][c4 + 0] = t.x; qs[r][c4 + 1] = t.y; qs[r][c4 + 2] = t.z; qs[r][c4 + 3] = t.w;
    }

    int aty = tid >> 4, atx = tid & 15;
    int bty = tid >> 4, btx = tid & 15;
    float acc[4][4] = {};
    const float* gp = d_gpow + h * S;
    const float* Mh = d_M + (h * NC + cidx) * (DH * DH);
    __syncthreads();

    // ---- intra-chunk: 2 key tiles of 32 ----
    for (int t = 0; t < 2; t++) {
        int m0 = s0 + t * 32;
        for (int i = tid; i < 32 * 16; i += 256) {
            int r = i >> 4;
            int c4 = (i & 15) * 4;
            float4 kv = *(const float4*)&k[(m0 + r) * D + h * DH + c4];
            ks[r][c4 + 0] = kv.x; ks[r][c4 + 1] = kv.y; ks[r][c4 + 2] = kv.z; ks[r][c4 + 3] = kv.w;
            float4 vv = *(const float4*)&v[(m0 + r) * D + h * DH + c4];
            vs[r][c4 + 0] = vv.x; vs[r][c4 + 1] = vv.y; vs[r][c4 + 2] = vv.z; vs[r][c4 + 3] = vv.w;
        }
        __syncthreads();

        float sv[4][2] = {};
#pragma unroll 16
        for (int d = 0; d < 64; d++) {
            float qr0 = qs[aty * 4 + 0][d];
            float qr1 = qs[aty * 4 + 1][d];
            float qr2 = qs[aty * 4 + 2][d];
            float qr3 = qs[aty * 4 + 3][d];
            float kc0 = ks[atx * 2 + 0][d];
            float kc1 = ks[atx * 2 + 1][d];
            sv[0][0] += qr0 * kc0; sv[0][1] += qr0 * kc1;
            sv[1][0] += qr1 * kc0; sv[1][1] += qr1 * kc1;
            sv[2][0] += qr2 * kc0; sv[2][1] += qr2 * kc1;
            sv[3][0] += qr3 * kc0; sv[3][1] += qr3 * kc1;
        }
#pragma unroll
        for (int r = 0; r < 4; r++)
#pragma unroll
            for (int c = 0; c < 2; c++) {
                int qi = s0 + aty * 4 + r;
                int kj = m0 + atx * 2 + c;
                int dist = qi - kj;
                ss[aty * 4 + r][atx * 2 + c] = (dist >= 0) ? sv[r][c] * gp[dist] : 0.0f;
            }
        __syncthreads();

#pragma unroll 8
        for (int j = 0; j < 32; j++) {
            float vr0 = vs[j][btx * 4 + 0];
            float vr1 = vs[j][btx * 4 + 1];
            float vr2 = vs[j][btx * 4 + 2];
            float vr3 = vs[j][btx * 4 + 3];
            float s0r = ss[bty * 4 + 0][j];
            float s1r = ss[bty * 4 + 1][j];
            float s2r = ss[bty * 4 + 2][j];
            float s3r = ss[bty * 4 + 3][j];
            acc[0][0] += s0r * vr0; acc[0][1] += s0r * vr1; acc[0][2] += s0r * vr2; acc[0][3] += s0r * vr3;
            acc[1][0] += s1r * vr0; acc[1][1] += s1r * vr1; acc[1][2] += s1r * vr2; acc[1][3] += s1r * vr3;
            acc[2][0] += s2r * vr0; acc[2][1] += s2r * vr1; acc[2][2] += s2r * vr2; acc[2][3] += s2r * vr3;
            acc[3][0] += s3r * vr0; acc[3][1] += s3r * vr1; acc[3][2] += s3r * vr2; acc[3][3] += s3r * vr3;
        }
        __syncthreads();
    }

    // ---- cross-chunk: ret += (gamma^(i+1) q_i) @ M ----
    if (cidx > 0) {
        for (int t2 = 0; t2 < 2; t2++) {
            for (int i = tid; i < 32 * 16; i += 256) {
                int r = i >> 4;
                int c4 = (i & 15) * 4;
                float4 mv = *(const float4*)&Mh[(t2 * 32 + r) * DH + c4];
                vs[r][c4 + 0] = mv.x; vs[r][c4 + 1] = mv.y; vs[r][c4 + 2] = mv.z; vs[r][c4 + 3] = mv.w;
            }
            for (int i = tid; i < 64 * 32; i += 256) {
                int r = i >> 5;
                int j = i & 31;
                ss[r][j] = qs[r][t2 * 32 + j] * gp[r + 1];
            }
            __syncthreads();
#pragma unroll 8
            for (int j = 0; j < 32; j++) {
                float vr0 = vs[j][btx * 4 + 0];
                float vr1 = vs[j][btx * 4 + 1];
                float vr2 = vs[j][btx * 4 + 2];
                float vr3 = vs[j][btx * 4 + 3];
                float s0r = ss[bty * 4 + 0][j];
                float s1r = ss[bty * 4 + 1][j];
                float s2r = ss[bty * 4 + 2][j];
                float s3r = ss[bty * 4 + 3][j];
                acc[0][0] += s0r * vr0; acc[0][1] += s0r * vr1; acc[0][2] += s0r * vr2; acc[0][3] += s0r * vr3;
                acc[1][0] += s1r * vr0; acc[1][1] += s1r * vr1; acc[1][2] += s1r * vr2; acc[1][3] += s1r * vr3;
                acc[2][0] += s2r * vr0; acc[2][1] += s2r * vr1; acc[2][2] += s2r * vr2; acc[2][3] += s2r * vr3;
                acc[3][0] += s3r * vr0; acc[3][1] += s3r * vr1; acc[3][2] += s3r * vr2; acc[3][3] += s3r * vr3;
            }
            __syncthreads();
        }
    }

    // ---- groupnorm over DH, write ----
#pragma unroll
    for (int r = 0; r < 4; r++)
#pragma unroll
        for (int c = 0; c < 4; c++)
            qs[bty * 4 + r][btx * 4 + c] = acc[r][c];
    __syncthreads();

    if (tid < 64) {
        int i = tid;
        float mu = 0.0f;
#pragma unroll 16
        for (int d = 0; d < 64; d++) mu += qs[i][d];
        mu *= (1.0f / 64.0f);
        float var = 0.0f;
#pragma unroll 16
        for (int d = 0; d < 64; d++) {
            float dd = qs[i][d] - mu;
            var += dd * dd;
        }
        var *= (1.0f / 64.0f);
        float rs = rsqrtf(var + 1e-6f);
#pragma unroll 16
        for (int d = 0; d < 64; d++)
            ret[(s0 + i) * D + h * DH + d] = (qs[i][d] - mu) * rs;
    }
}

// ---------------- final: out[s] = sigmoid(x[s,:] . Wout + bout) ----------------
__global__ void final_kernel(const float* __restrict__ Wout, const float* __restrict__ bout,
                             float* __restrict__ out) {
    int row = blockIdx.x;
    int t = threadIdx.x;   // 64
    float s = 0.0f;
    for (int i = t; i < D; i += 64) s += d_x[row * D + i] * Wout[i];
    __shared__ float red[64];
    red[t] = s;
    __syncthreads();
    for (int o = 32; o > 0; o >>= 1) {
        if (t < o) red[t] += red[t + o];
        __syncthreads();
    }
    if (t == 0) out[row] = 1.0f / (1.0f + expf(-(red[0] + bout[0])));
}

// ---------------- host orchestration ----------------
extern "C" void kernel_launch(void* const* d_in, const int* in_sizes, int n_in,
                              void* d_out, int out_size) {
    const float* x_in  = (const float*)d_in[0];
    const float* pe    = (const float*)d_in[1];
    const float* Wq    = (const float*)d_in[2];
    const float* bq    = (const float*)d_in[3];
    const float* Wk    = (const float*)d_in[4];
    const float* bk    = (const float*)d_in[5];
    const float* Wv    = (const float*)d_in[6];
    const float* bv    = (const float*)d_in[7];
    const float* Wg    = (const float*)d_in[8];
    const float* bg    = (const float*)d_in[9];
    const float* Wo    = (const float*)d_in[10];
    const float* bo    = (const float*)d_in[11];
    const float* ln1w  = (const float*)d_in[12];
    const float* ln1b  = (const float*)d_in[13];
    const float* ln2w  = (const float*)d_in[14];
    const float* ln2b  = (const float*)d_in[15];
    const float* W1    = (const float*)d_in[16];
    const float* b1    = (const float*)d_in[17];
    const float* W2    = (const float*)d_in[18];
    const float* b2    = (const float*)d_in[19];
    const float* Wout  = (const float*)d_in[20];
    const float* bout  = (const float*)d_in[21];
    float* out = (float*)d_out;

    void *px_, *py_, *pq_, *pk_, *pv_, *pg_, *pret_, *pff_;
    cudaGetSymbolAddress(&px_,  d_x);
    cudaGetSymbolAddress(&py_,  d_y);
    cudaGetSymbolAddress(&pq_,  d_q);
    cudaGetSymbolAddress(&pk_,  d_k);
    cudaGetSymbolAddress(&pv_,  d_v);
    cudaGetSymbolAddress(&pg_,  d_g);
    cudaGetSymbolAddress(&pret_, d_ret);
    cudaGetSymbolAddress(&pff_, d_ff);
    float* px   = (float*)px_;
    float* py   = (float*)py_;
    float* pq   = (float*)pq_;
    float* pk   = (float*)pk_;
    float* pv   = (float*)pv_;
    float* pg   = (float*)pg_;
    float* pret = (float*)pret_;
    float* pff  = (float*)pff_;

    init_tables_kernel<<<(S * 32 + 255) / 256, 256>>>();
    add_pos_kernel<<<(S * D + 255) / 256, 256>>>(x_in, pe);

    dim3 grid_qkvg(D / 128, S / 128, 4);     // (4,16,4) = 256 blocks
    dim3 grid_ff1(FF / 128, S / 128);        // (16,16)  = 256 blocks
    dim3 grid_64(D / 128, S / 64);           // (4,32)   = 128 blocks
    dim3 grid_ret(NC, H);                    // (32,8)   = 256 blocks

    for (int l = 0; l < L; l++) {
        layernorm_kernel<<<S, 256>>>(px, ln1w + l * D, ln1b + l * D, py, 1e-5f);

        qkvg_gemm<<<grid_qkvg, 256>>>(py,
            Wq + l * D * D, Wk + l * D * D, Wv + l * D * D, Wg + l * D * D,
            bq + l * D, bk + l * D, bv + l * D, bg + l * D);

        chunk_kv_kernel<<<grid_ret, 256>>>(pk, pv);
        scan_kernel<<<(H * DH * DH + 255) / 256, 256>>>();
        retn_kernel<<<grid_ret, 256>>>(pq, pk, pv, pret);

        // x += (g*ret) @ Wo + bo   (A-side elementwise product fused)
        gemm64_res<D, true><<<grid_64, 256>>>(pg, pret, Wo + l * D * D, bo + l * D, px);

        layernorm_kernel<<<S, 256>>>(px, ln2w + l * D, ln2b + l * D, py, 1e-5f);
        ffn1_gemm<<<grid_ff1, 256>>>(py, W1 + l * D * FF, b1 + l * FF);
        gemm64_res<FF, false><<<grid_64, 256>>>(pff, pff, W2 + l * FF * D, b2 + l * D, px);
    }

    final_kernel<<<S, 64>>>(Wout, bout, out);
}